// round 14
// baseline (speedup 1.0000x reference)
#include <cuda_runtime.h>

#define N_NODES 4096
#define E_EDGES 16384
#define HID 128

typedef unsigned long long ull;

// ---------------- scratch (device globals; zero-initialized at module load).
// Every kernel re-zeroes the scratch it consumed, so each graph replay starts
// from the same (zeroed) state: deterministic.
__device__ __align__(16) float g_h1[N_NODES * HID];
__device__ __align__(16) float g_h2[N_NODES * HID];
__device__ __align__(16) float g_agg[N_NODES * HID];
__device__ __align__(16) float g_root1[N_NODES * HID];
__device__ __align__(16) float g_root2[N_NODES * HID];
__device__ __align__(16) float g_root3[N_NODES * 2];
__device__ __align__(16) float g_agg3[N_NODES * 2];
__device__ float g_cnt[N_NODES];

// ---------------- packed fp32x2 helpers (sm_100+) ----------------
__device__ __forceinline__ ull pk2(float lo, float hi) {
    ull r; asm("mov.b64 %0, {%1, %2};" : "=l"(r) : "f"(lo), "f"(hi)); return r;
}
__device__ __forceinline__ void upk2(ull v, float &lo, float &hi) {
    asm("mov.b64 {%0, %1}, %2;" : "=f"(lo), "=f"(hi) : "l"(v));
}
__device__ __forceinline__ ull ffma2(ull a, ull b, ull c) {
    ull r; asm("fma.rn.f32x2 %0, %1, %2, %3;" : "=l"(r) : "l"(a), "l"(b), "l"(c)); return r;
}
// relu(a0*w0 + a1*w1 + b) on a packed pair, single asm block.
__device__ __forceinline__ ull genrelu(ull a0, ull w0, ull a1, ull w1, ull b) {
    ull r;
    asm("{\n\t"
        ".reg .b64 z;\n\t"
        ".reg .f32 lo, hi;\n\t"
        "fma.rn.f32x2 z, %1, %2, %5;\n\t"
        "fma.rn.f32x2 z, %3, %4, z;\n\t"
        "mov.b64 {lo, hi}, z;\n\t"
        "max.f32 lo, lo, 0f00000000;\n\t"
        "max.f32 hi, hi, 0f00000000;\n\t"
        "mov.b64 %0, {lo, hi};\n\t"
        "}"
        : "=l"(r) : "l"(a0), "l"(w0), "l"(a1), "l"(w1), "l"(b));
    return r;
}

// ---------------- root GEMM for layer 1: g_root1 = x @ r1 + c1 (side stream) ----------------
__global__ void k_root1(const float* __restrict__ x, const float* __restrict__ r1,
                        const float* __restrict__ c1) {
    int t = blockIdx.x * blockDim.x + threadIdx.x;   // N*32 threads
    int n = t >> 5;
    int o4 = (t & 31) << 2;
    float4 xs = __ldg((const float4*)(x + 4 * n));
    float xv[4] = {xs.x, xs.y, xs.z, xs.w};
    float4 root = __ldg((const float4*)(c1 + o4));
#pragma unroll
    for (int i = 0; i < 4; i++) {
        float4 rv = __ldg((const float4*)(r1 + i * 128 + o4));
        root.x = fmaf(xv[i], rv.x, root.x);
        root.y = fmaf(xv[i], rv.y, root.y);
        root.z = fmaf(xv[i], rv.z, root.z);
        root.w = fmaf(xv[i], rv.w, root.w);
    }
    *(float4*)(g_root1 + n * 128 + o4) = root;
}

// ---------------- layer 1 edge: IN=4 -> 128, warp-batched (8 edges/warp) ----------------
__global__ void __launch_bounds__(256) k_l1_edge(
        const float* __restrict__ x, const float* __restrict__ ea,
        const int* __restrict__ src, const int* __restrict__ dst,
        const float* __restrict__ w1, const float* __restrict__ b1) {
    const int lane = threadIdx.x & 31;
    const int warp = threadIdx.x >> 5;
    const int ebase = (blockIdx.x * 8 + warp) * 8;   // 256 blocks * 8 warps * 8 edges
    const int o4 = lane << 2;

    float4 w0v[4], w1v[4], bv[4];
#pragma unroll
    for (int i = 0; i < 4; i++) {
        int idx = i * 128 + o4;
        w0v[i] = __ldg((const float4*)(w1 + idx));
        w1v[i] = __ldg((const float4*)(w1 + 512 + idx));
        bv[i]  = __ldg((const float4*)(b1 + idx));
    }

#pragma unroll
    for (int e = 0; e < 8; e++) {
        int ei = ebase + e;
        float2 a = __ldg((const float2*)(ea + 2 * ei));
        int s = __ldg(&src[ei]);
        int d = __ldg(&dst[ei]);
        float4 xs = __ldg((const float4*)(x + 4 * s));
        float xv[4] = {xs.x, xs.y, xs.z, xs.w};
        float4 acc = make_float4(0.f, 0.f, 0.f, 0.f);
#pragma unroll
        for (int i = 0; i < 4; i++) {
            acc.x = fmaf(xv[i], fmaxf(fmaf(a.y, w1v[i].x, fmaf(a.x, w0v[i].x, bv[i].x)), 0.f), acc.x);
            acc.y = fmaf(xv[i], fmaxf(fmaf(a.y, w1v[i].y, fmaf(a.x, w0v[i].y, bv[i].y)), 0.f), acc.y);
            acc.z = fmaf(xv[i], fmaxf(fmaf(a.y, w1v[i].z, fmaf(a.x, w0v[i].z, bv[i].z)), 0.f), acc.z);
            acc.w = fmaf(xv[i], fmaxf(fmaf(a.y, w1v[i].w, fmaf(a.x, w0v[i].w, bv[i].w)), 0.f), acc.w);
        }
        atomicAdd((float4*)(g_agg + d * 128 + o4), acc);
        if (lane == e) atomicAdd(&g_cnt[d], 1.f);   // fused in-degree count
    }
}

// ---------------- layer 1 node: h1 = relu(agg/cnt + root1); re-zero agg ----------------
__global__ void k_l1_node() {
    int t = blockIdx.x * blockDim.x + threadIdx.x;   // N*32 threads
    int n = t >> 5;
    int o4 = (t & 31) << 2;
    int base = n * 128 + o4;
    float inv = 1.f / fmaxf(g_cnt[n], 1.f);
    float4 ag = *(const float4*)(g_agg + base);
    float4 rt = *(const float4*)(g_root1 + base);
    float4 h;
    h.x = fmaxf(fmaf(ag.x, inv, rt.x), 0.f);
    h.y = fmaxf(fmaf(ag.y, inv, rt.y), 0.f);
    h.z = fmaxf(fmaf(ag.z, inv, rt.z), 0.f);
    h.w = fmaxf(fmaf(ag.w, inv, rt.w), 0.f);
    *(float4*)(g_h1 + base) = h;
    *(float4*)(g_agg + base) = make_float4(0.f, 0.f, 0.f, 0.f);   // ready for layer 2
}

// ---------------- root GEMM for layer 2: g_root2 = h1 @ r2 + c2 (side stream) ----------------
__global__ void __launch_bounds__(128) k_root2(const float* __restrict__ r2,
                                               const float* __restrict__ c2) {
    const int lane = threadIdx.x & 31;
    const int warp = threadIdx.x >> 5;
    const int nbase = (blockIdx.x * 4 + warp) * 2;   // 512 blocks * 4 warps * 2 nodes = 4096
    const int o4 = lane << 2;

    const float* hp0 = g_h1 + nbase * 128;
    const float* hp1 = hp0 + 128;

    ull a00 = 0ull, a01 = 0ull, a10 = 0ull, a11 = 0ull;
    const ull* rp = (const ull*)r2 + (lane << 1);

    for (int i4 = 0; i4 < 128; i4 += 4) {
        float4 h0 = *(const float4*)(hp0 + i4);
        float4 h1v = *(const float4*)(hp1 + i4);
        float h0a[4] = {h0.x, h0.y, h0.z, h0.w};
        float h1a[4] = {h1v.x, h1v.y, h1v.z, h1v.w};
#pragma unroll
        for (int ii = 0; ii < 4; ii++) {
            ulonglong2 rv = __ldg((const ulonglong2*)(rp + (i4 + ii) * 64));
            ull hd0 = pk2(h0a[ii], h0a[ii]);
            ull hd1 = pk2(h1a[ii], h1a[ii]);
            a00 = ffma2(hd0, rv.x, a00);
            a01 = ffma2(hd0, rv.y, a01);
            a10 = ffma2(hd1, rv.x, a10);
            a11 = ffma2(hd1, rv.y, a11);
        }
    }

    float4 cv = __ldg((const float4*)(c2 + o4));
#pragma unroll
    for (int e = 0; e < 2; e++) {
        int base = (nbase + e) * 128 + o4;
        float v0, v1, v2, v3;
        upk2(e ? a10 : a00, v0, v1);
        upk2(e ? a11 : a01, v2, v3);
        float4 r;
        r.x = v0 + cv.x; r.y = v1 + cv.y; r.z = v2 + cv.z; r.w = v3 + cv.w;
        *(float4*)(g_root2 + base) = r;
    }
}

// ---------------- layer 2 edge: THE hot kernel (R10 form — best measured) ----------------
// Block = 8 warps = 64 edges x one 32-i quarter. W slice (48 KB) in static smem;
// h via LDG float2 (L1-resident). 1024 blocks; 2 CTAs/SM.
__global__ void __launch_bounds__(256, 2) k_l2_edge(
        const float* __restrict__ h1, const float* __restrict__ ea,
        const int* __restrict__ src, const int* __restrict__ dst,
        const float* __restrict__ w2, const float* __restrict__ b2,
        float* __restrict__ agg) {
    __shared__ __align__(16) float smW[3 * 32 * 128];   // W0 | W1 | B slices, 48 KB

    const int tid  = threadIdx.x;
    const int lane = tid & 31;
    const int warp = tid >> 5;
    const int ibase = (blockIdx.x & 3) << 5;     // i-quarter: {0,32,64,96}
    const int gblk  = blockIdx.x >> 2;           // edge block 0..255
    const int ebase = gblk * 64 + warp * 8;      // 8 edges per warp

    // cooperative stage: 3 x 1024 float4, 12 per thread
    {
        const float4* gW0 = (const float4*)(w2 + ibase * 128);
        const float4* gW1 = (const float4*)(w2 + 16384 + ibase * 128);
        const float4* gB  = (const float4*)(b2 + ibase * 128);
        float4* sm4 = (float4*)smW;
#pragma unroll
        for (int k = 0; k < 4; k++) {
            sm4[tid + k * 256]        = __ldg(gW0 + tid + k * 256);
            sm4[tid + k * 256 + 1024] = __ldg(gW1 + tid + k * 256);
            sm4[tid + k * 256 + 2048] = __ldg(gB  + tid + k * 256);
        }
    }

    ull ea0p[8], ea1p[8];
    const float* hp[8];
#pragma unroll
    for (int e = 0; e < 8; e++) {
        float2 a = __ldg((const float2*)(ea + 2 * (ebase + e)));
        ea0p[e] = pk2(a.x, a.x);
        ea1p[e] = pk2(a.y, a.y);
        hp[e] = h1 + __ldg(&src[ebase + e]) * 128 + ibase;
    }

    __syncthreads();

    ull acc0[8], acc1[8];
#pragma unroll
    for (int e = 0; e < 8; e++) { acc0[e] = 0ull; acc1[e] = 0ull; }

    const ull* sW0 = (const ull*)smW + (lane << 1);          // 2048 ull per slice
    const ull* sW1 = sW0 + 2048;
    const ull* sB  = sW0 + 4096;

    for (int i2 = 0; i2 < 32; i2 += 2) {
        float2 hv[8];
#pragma unroll
        for (int e = 0; e < 8; e++)
            hv[e] = __ldg((const float2*)(hp[e] + i2));
#pragma unroll
        for (int ii = 0; ii < 2; ii++) {
            const int woff = (i2 + ii) * 64;
            ulonglong2 w0 = *(const ulonglong2*)(sW0 + woff);
            ulonglong2 w1 = *(const ulonglong2*)(sW1 + woff);
            ulonglong2 bv = *(const ulonglong2*)(sB  + woff);
#pragma unroll
            for (int e = 0; e < 8; e++) {
                float h = ii ? hv[e].y : hv[e].x;
                ull hd = pk2(h, h);
                ull z0 = genrelu(ea0p[e], w0.x, ea1p[e], w1.x, bv.x);
                ull z1 = genrelu(ea0p[e], w0.y, ea1p[e], w1.y, bv.y);
                acc0[e] = ffma2(hd, z0, acc0[e]);
                acc1[e] = ffma2(hd, z1, acc1[e]);
            }
        }
    }

    const int o4 = lane << 2;
#pragma unroll
    for (int e = 0; e < 8; e++) {
        float4 v;
        upk2(acc0[e], v.x, v.y);
        upk2(acc1[e], v.z, v.w);
        int d = __ldg(&dst[ebase + e]);
        atomicAdd((float4*)(agg + d * 128 + o4), v);
    }
}

// ---------------- layer 2 combine: h2 = relu(agg/cnt + root2); re-zero agg ----------------
__global__ void k_l2_combine() {
    int t = blockIdx.x * blockDim.x + threadIdx.x;   // N*32 threads
    int n = t >> 5;
    int o4 = (t & 31) << 2;
    int base = n * 128 + o4;
    float inv = 1.f / fmaxf(g_cnt[n], 1.f);
    float4 ag = *(const float4*)(g_agg + base);
    float4 rt = *(const float4*)(g_root2 + base);
    float4 h;
    h.x = fmaxf(fmaf(ag.x, inv, rt.x), 0.f);
    h.y = fmaxf(fmaf(ag.y, inv, rt.y), 0.f);
    h.z = fmaxf(fmaf(ag.z, inv, rt.z), 0.f);
    h.w = fmaxf(fmaf(ag.w, inv, rt.w), 0.f);
    *(float4*)(g_h2 + base) = h;
    *(float4*)(g_agg + base) = make_float4(0.f, 0.f, 0.f, 0.f);   // clean for next replay
}

// ---------------- root GEMM for layer 3: g_root3 = h2 @ r3 + c3 (side stream) ----------------
__global__ void k_root3(const float* __restrict__ r3, const float* __restrict__ c3) {
    const int lane = threadIdx.x & 31;
    const int warp = threadIdx.x >> 5;
    const int n = blockIdx.x * 8 + warp;   // 512 blocks * 8 warps = 4096 nodes
    float s0 = 0.f, s1 = 0.f;
#pragma unroll
    for (int rep = 0; rep < 4; rep++) {
        int i = rep * 32 + lane;
        float h = g_h2[n * 128 + i];
        s0 = fmaf(h, __ldg(&r3[2 * i + 0]), s0);
        s1 = fmaf(h, __ldg(&r3[2 * i + 1]), s1);
    }
#pragma unroll
    for (int off = 16; off > 0; off >>= 1) {
        s0 += __shfl_down_sync(0xFFFFFFFFu, s0, off);
        s1 += __shfl_down_sync(0xFFFFFFFFu, s1, off);
    }
    if (lane == 0) {
        g_root3[2 * n + 0] = s0 + __ldg(&c3[0]);
        g_root3[2 * n + 1] = s1 + __ldg(&c3[1]);
    }
}

// ---------------- layer 3 edge: 128 -> 2, warp per edge ----------------
__global__ void k_l3_edge(const float* __restrict__ ea,
                          const int* __restrict__ src, const int* __restrict__ dst,
                          const float* __restrict__ w3, const float* __restrict__ b3) {
    const int lane = threadIdx.x & 31;
    const int warp = threadIdx.x >> 5;
    const int e = blockIdx.x * 8 + warp;   // 2048 blocks * 8 warps = 16384 edges
    float2 a = __ldg((const float2*)(ea + 2 * e));
    int s = __ldg(&src[e]);
    float s0 = 0.f, s1 = 0.f;
#pragma unroll
    for (int rep = 0; rep < 4; rep++) {
        int i = rep * 32 + lane;
        float h = g_h2[s * 128 + i];
        int idx = 2 * i;
        float z0 = fmaf(a.y, __ldg(&w3[256 + idx]),     fmaf(a.x, __ldg(&w3[idx]),     __ldg(&b3[idx])));
        float z1 = fmaf(a.y, __ldg(&w3[256 + idx + 1]), fmaf(a.x, __ldg(&w3[idx + 1]), __ldg(&b3[idx + 1])));
        s0 = fmaf(h, fmaxf(z0, 0.f), s0);
        s1 = fmaf(h, fmaxf(z1, 0.f), s1);
    }
#pragma unroll
    for (int off = 16; off > 0; off >>= 1) {
        s0 += __shfl_down_sync(0xFFFFFFFFu, s0, off);
        s1 += __shfl_down_sync(0xFFFFFFFFu, s1, off);
    }
    if (lane == 0) {
        int d = __ldg(&dst[e]);
        atomicAdd(&g_agg3[2 * d + 0], s0);
        atomicAdd(&g_agg3[2 * d + 1], s1);
    }
}

// ---------------- layer 3 node: out = agg3/cnt + root3; cleanup scratch (elementwise) ----
__global__ void k_l3_node(float* __restrict__ out) {
    int n = blockIdx.x * blockDim.x + threadIdx.x;   // 4096 threads
    float inv = 1.f / fmaxf(g_cnt[n], 1.f);
    out[2 * n + 0] = fmaf(g_agg3[2 * n + 0], inv, g_root3[2 * n + 0]);
    out[2 * n + 1] = fmaf(g_agg3[2 * n + 1], inv, g_root3[2 * n + 1]);
    // cleanup for next replay
    g_agg3[2 * n + 0] = 0.f;
    g_agg3[2 * n + 1] = 0.f;
    g_cnt[n] = 0.f;
}

// ---------------- launch ----------------
// Side-stream resources: created once, on the FIRST (correctness) call — i.e.
// outside graph capture. The WORK issued per call is identical every time.
static cudaStream_t g_side = nullptr;
static cudaEvent_t  g_ev[6] = {nullptr, nullptr, nullptr, nullptr, nullptr, nullptr};

extern "C" void kernel_launch(void* const* d_in, const int* in_sizes, int n_in,
                              void* d_out, int out_size) {
    const float* x   = (const float*)d_in[0];
    const float* ea  = (const float*)d_in[1];
    const int*   src = (const int*)d_in[2];
    const int*   dst = (const int*)d_in[3];
    const float* w1  = (const float*)d_in[4];
    const float* b1  = (const float*)d_in[5];
    const float* r1  = (const float*)d_in[6];
    const float* c1  = (const float*)d_in[7];
    const float* w2  = (const float*)d_in[8];
    const float* b2  = (const float*)d_in[9];
    const float* r2  = (const float*)d_in[10];
    const float* c2  = (const float*)d_in[11];
    const float* w3  = (const float*)d_in[12];
    const float* b3  = (const float*)d_in[13];
    const float* r3  = (const float*)d_in[14];
    const float* c3  = (const float*)d_in[15];
    float* out = (float*)d_out;

    if (g_side == nullptr) {
        cudaStreamCreateWithFlags(&g_side, cudaStreamNonBlocking);
        for (int i = 0; i < 6; i++)
            cudaEventCreateWithFlags(&g_ev[i], cudaEventDisableTiming);
    }

    float* aggp;
    cudaGetSymbolAddress((void**)&aggp, g_agg);
    float* h1p;
    cudaGetSymbolAddress((void**)&h1p, g_h1);

    // ---- layer 1: root1 (side) || l1_edge (main) ----
    cudaEventRecord(g_ev[0], 0);
    cudaStreamWaitEvent(g_side, g_ev[0], 0);
    k_root1<<<512, 256, 0, g_side>>>(x, r1, c1);
    k_l1_edge<<<256, 256>>>(x, ea, src, dst, w1, b1);
    cudaEventRecord(g_ev[1], g_side);
    cudaStreamWaitEvent(0, g_ev[1], 0);
    k_l1_node<<<512, 256>>>();

    // ---- layer 2: root2 (side) || l2_edge (main) ----
    cudaEventRecord(g_ev[2], 0);
    cudaStreamWaitEvent(g_side, g_ev[2], 0);
    k_root2<<<512, 128, 0, g_side>>>(r2, c2);
    k_l2_edge<<<1024, 256>>>(h1p, ea, src, dst, w2, b2, aggp);
    cudaEventRecord(g_ev[3], g_side);
    cudaStreamWaitEvent(0, g_ev[3], 0);
    k_l2_combine<<<512, 256>>>();

    // ---- layer 3: root3 (side) || l3_edge (main) ----
    cudaEventRecord(g_ev[4], 0);
    cudaStreamWaitEvent(g_side, g_ev[4], 0);
    k_root3<<<512, 256, 0, g_side>>>(r3, c3);
    k_l3_edge<<<E_EDGES / 8, 256>>>(ea, src, dst, w3, b3);
    cudaEventRecord(g_ev[5], g_side);
    cudaStreamWaitEvent(0, g_ev[5], 0);
    k_l3_node<<<N_NODES / 256, 256>>>(out);
}

// round 15
// speedup vs baseline: 1.0829x; 1.0829x over previous
#include <cuda_runtime.h>

#define N_NODES 4096
#define E_EDGES 16384
#define HID 128

typedef unsigned long long ull;

// ---------------- scratch (device globals; zero-initialized at module load).
// Every kernel re-zeroes the scratch it consumed, so each graph replay starts
// from the same (zeroed) state: deterministic.
__device__ __align__(16) float g_h1[N_NODES * HID];
__device__ __align__(16) float g_agg[N_NODES * HID];
__device__ __align__(16) float g_root2[N_NODES * HID];
__device__ __align__(16) float g_agg3[N_NODES * 2];
__device__ float g_cnt[N_NODES];

// ---------------- packed fp32x2 helpers (sm_100+) ----------------
__device__ __forceinline__ ull pk2(float lo, float hi) {
    ull r; asm("mov.b64 %0, {%1, %2};" : "=l"(r) : "f"(lo), "f"(hi)); return r;
}
__device__ __forceinline__ void upk2(ull v, float &lo, float &hi) {
    asm("mov.b64 {%0, %1}, %2;" : "=f"(lo), "=f"(hi) : "l"(v));
}
__device__ __forceinline__ ull ffma2(ull a, ull b, ull c) {
    ull r; asm("fma.rn.f32x2 %0, %1, %2, %3;" : "=l"(r) : "l"(a), "l"(b), "l"(c)); return r;
}
// relu(a0*w0 + a1*w1 + b) on a packed pair, single asm block.
__device__ __forceinline__ ull genrelu(ull a0, ull w0, ull a1, ull w1, ull b) {
    ull r;
    asm("{\n\t"
        ".reg .b64 z;\n\t"
        ".reg .f32 lo, hi;\n\t"
        "fma.rn.f32x2 z, %1, %2, %5;\n\t"
        "fma.rn.f32x2 z, %3, %4, z;\n\t"
        "mov.b64 {lo, hi}, z;\n\t"
        "max.f32 lo, lo, 0f00000000;\n\t"
        "max.f32 hi, hi, 0f00000000;\n\t"
        "mov.b64 %0, {lo, hi};\n\t"
        "}"
        : "=l"(r) : "l"(a0), "l"(w0), "l"(a1), "l"(w1), "l"(b));
    return r;
}

// ---------------- layer 1 edge: IN=4 -> 128, warp-batched (8 edges/warp) ----------------
// W/b held in registers, reused by 8 edges. Also counts in-degree.
__global__ void __launch_bounds__(256) k_l1_edge(
        const float* __restrict__ x, const float* __restrict__ ea,
        const int* __restrict__ src, const int* __restrict__ dst,
        const float* __restrict__ w1, const float* __restrict__ b1) {
    const int lane = threadIdx.x & 31;
    const int warp = threadIdx.x >> 5;
    const int ebase = (blockIdx.x * 8 + warp) * 8;   // 256 blocks * 8 warps * 8 edges
    const int o4 = lane << 2;

    float4 w0v[4], w1v[4], bv[4];
#pragma unroll
    for (int i = 0; i < 4; i++) {
        int idx = i * 128 + o4;
        w0v[i] = __ldg((const float4*)(w1 + idx));
        w1v[i] = __ldg((const float4*)(w1 + 512 + idx));
        bv[i]  = __ldg((const float4*)(b1 + idx));
    }

#pragma unroll
    for (int e = 0; e < 8; e++) {
        int ei = ebase + e;
        float2 a = __ldg((const float2*)(ea + 2 * ei));
        int s = __ldg(&src[ei]);
        int d = __ldg(&dst[ei]);
        float4 xs = __ldg((const float4*)(x + 4 * s));
        float xv[4] = {xs.x, xs.y, xs.z, xs.w};
        float4 acc = make_float4(0.f, 0.f, 0.f, 0.f);
#pragma unroll
        for (int i = 0; i < 4; i++) {
            acc.x = fmaf(xv[i], fmaxf(fmaf(a.y, w1v[i].x, fmaf(a.x, w0v[i].x, bv[i].x)), 0.f), acc.x);
            acc.y = fmaf(xv[i], fmaxf(fmaf(a.y, w1v[i].y, fmaf(a.x, w0v[i].y, bv[i].y)), 0.f), acc.y);
            acc.z = fmaf(xv[i], fmaxf(fmaf(a.y, w1v[i].z, fmaf(a.x, w0v[i].z, bv[i].z)), 0.f), acc.z);
            acc.w = fmaf(xv[i], fmaxf(fmaf(a.y, w1v[i].w, fmaf(a.x, w0v[i].w, bv[i].w)), 0.f), acc.w);
        }
        atomicAdd((float4*)(g_agg + d * 128 + o4), acc);
        if (lane == e) atomicAdd(&g_cnt[d], 1.f);   // fused in-degree count
    }
}

// ---------------- layer 1 node: h1 = relu(agg/cnt + x@r1 + c1); re-zero agg ----------------
__global__ void k_l1_node(const float* __restrict__ x, const float* __restrict__ r1,
                          const float* __restrict__ c1) {
    int t = blockIdx.x * blockDim.x + threadIdx.x;   // N*32 threads
    int n = t >> 5;
    int o4 = (t & 31) << 2;
    int base = n * 128 + o4;
    float inv = 1.f / fmaxf(g_cnt[n], 1.f);
    float4 xs = __ldg((const float4*)(x + 4 * n));
    float xv[4] = {xs.x, xs.y, xs.z, xs.w};
    float4 ag = *(const float4*)(g_agg + base);
    float4 root = __ldg((const float4*)(c1 + o4));
#pragma unroll
    for (int i = 0; i < 4; i++) {
        float4 rv = __ldg((const float4*)(r1 + i * 128 + o4));
        root.x = fmaf(xv[i], rv.x, root.x);
        root.y = fmaf(xv[i], rv.y, root.y);
        root.z = fmaf(xv[i], rv.z, root.z);
        root.w = fmaf(xv[i], rv.w, root.w);
    }
    float4 h;
    h.x = fmaxf(fmaf(ag.x, inv, root.x), 0.f);
    h.y = fmaxf(fmaf(ag.y, inv, root.y), 0.f);
    h.z = fmaxf(fmaf(ag.z, inv, root.z), 0.f);
    h.w = fmaxf(fmaf(ag.w, inv, root.w), 0.f);
    *(float4*)(g_h1 + base) = h;
    *(float4*)(g_agg + base) = make_float4(0.f, 0.f, 0.f, 0.f);   // ready for layer 2
}

// ---------------- root GEMM for layer 2: g_root2 = h1 @ r2 + c2 (side stream) ----------------
__global__ void __launch_bounds__(128) k_root2(const float* __restrict__ r2,
                                               const float* __restrict__ c2) {
    const int lane = threadIdx.x & 31;
    const int warp = threadIdx.x >> 5;
    const int nbase = (blockIdx.x * 4 + warp) * 2;   // 512 blocks * 4 warps * 2 nodes = 4096
    const int o4 = lane << 2;

    const float* hp0 = g_h1 + nbase * 128;
    const float* hp1 = hp0 + 128;

    ull a00 = 0ull, a01 = 0ull, a10 = 0ull, a11 = 0ull;
    const ull* rp = (const ull*)r2 + (lane << 1);

    for (int i4 = 0; i4 < 128; i4 += 4) {
        float4 h0 = *(const float4*)(hp0 + i4);
        float4 h1v = *(const float4*)(hp1 + i4);
        float h0a[4] = {h0.x, h0.y, h0.z, h0.w};
        float h1a[4] = {h1v.x, h1v.y, h1v.z, h1v.w};
#pragma unroll
        for (int ii = 0; ii < 4; ii++) {
            ulonglong2 rv = __ldg((const ulonglong2*)(rp + (i4 + ii) * 64));
            ull hd0 = pk2(h0a[ii], h0a[ii]);
            ull hd1 = pk2(h1a[ii], h1a[ii]);
            a00 = ffma2(hd0, rv.x, a00);
            a01 = ffma2(hd0, rv.y, a01);
            a10 = ffma2(hd1, rv.x, a10);
            a11 = ffma2(hd1, rv.y, a11);
        }
    }

    float4 cv = __ldg((const float4*)(c2 + o4));
#pragma unroll
    for (int e = 0; e < 2; e++) {
        int base = (nbase + e) * 128 + o4;
        float v0, v1, v2, v3;
        upk2(e ? a10 : a00, v0, v1);
        upk2(e ? a11 : a01, v2, v3);
        float4 r;
        r.x = v0 + cv.x; r.y = v1 + cv.y; r.z = v2 + cv.z; r.w = v3 + cv.w;
        *(float4*)(g_root2 + base) = r;
    }
}

// ---------------- layer 2 edge: THE hot kernel (R10 form — best measured) ----------------
// Block = 8 warps = 64 edges x one 32-i quarter. W slice (48 KB) in static smem;
// h via LDG float2 (L1-resident). 1024 blocks; 2 CTAs/SM.
__global__ void __launch_bounds__(256, 2) k_l2_edge(
        const float* __restrict__ h1, const float* __restrict__ ea,
        const int* __restrict__ src, const int* __restrict__ dst,
        const float* __restrict__ w2, const float* __restrict__ b2,
        float* __restrict__ agg) {
    __shared__ __align__(16) float smW[3 * 32 * 128];   // W0 | W1 | B slices, 48 KB

    const int tid  = threadIdx.x;
    const int lane = tid & 31;
    const int warp = tid >> 5;
    const int ibase = (blockIdx.x & 3) << 5;     // i-quarter: {0,32,64,96}
    const int gblk  = blockIdx.x >> 2;           // edge block 0..255
    const int ebase = gblk * 64 + warp * 8;      // 8 edges per warp

    // cooperative stage: 3 x 1024 float4, 12 per thread
    {
        const float4* gW0 = (const float4*)(w2 + ibase * 128);
        const float4* gW1 = (const float4*)(w2 + 16384 + ibase * 128);
        const float4* gB  = (const float4*)(b2 + ibase * 128);
        float4* sm4 = (float4*)smW;
#pragma unroll
        for (int k = 0; k < 4; k++) {
            sm4[tid + k * 256]        = __ldg(gW0 + tid + k * 256);
            sm4[tid + k * 256 + 1024] = __ldg(gW1 + tid + k * 256);
            sm4[tid + k * 256 + 2048] = __ldg(gB  + tid + k * 256);
        }
    }

    ull ea0p[8], ea1p[8];
    const float* hp[8];
#pragma unroll
    for (int e = 0; e < 8; e++) {
        float2 a = __ldg((const float2*)(ea + 2 * (ebase + e)));
        ea0p[e] = pk2(a.x, a.x);
        ea1p[e] = pk2(a.y, a.y);
        hp[e] = h1 + __ldg(&src[ebase + e]) * 128 + ibase;
    }

    __syncthreads();

    ull acc0[8], acc1[8];
#pragma unroll
    for (int e = 0; e < 8; e++) { acc0[e] = 0ull; acc1[e] = 0ull; }

    const ull* sW0 = (const ull*)smW + (lane << 1);          // 2048 ull per slice
    const ull* sW1 = sW0 + 2048;
    const ull* sB  = sW0 + 4096;

    for (int i2 = 0; i2 < 32; i2 += 2) {
        float2 hv[8];
#pragma unroll
        for (int e = 0; e < 8; e++)
            hv[e] = __ldg((const float2*)(hp[e] + i2));
#pragma unroll
        for (int ii = 0; ii < 2; ii++) {
            const int woff = (i2 + ii) * 64;
            ulonglong2 w0 = *(const ulonglong2*)(sW0 + woff);
            ulonglong2 w1 = *(const ulonglong2*)(sW1 + woff);
            ulonglong2 bv = *(const ulonglong2*)(sB  + woff);
#pragma unroll
            for (int e = 0; e < 8; e++) {
                float h = ii ? hv[e].y : hv[e].x;
                ull hd = pk2(h, h);
                ull z0 = genrelu(ea0p[e], w0.x, ea1p[e], w1.x, bv.x);
                ull z1 = genrelu(ea0p[e], w0.y, ea1p[e], w1.y, bv.y);
                acc0[e] = ffma2(hd, z0, acc0[e]);
                acc1[e] = ffma2(hd, z1, acc1[e]);
            }
        }
    }

    const int o4 = lane << 2;
#pragma unroll
    for (int e = 0; e < 8; e++) {
        float4 v;
        upk2(acc0[e], v.x, v.y);
        upk2(acc1[e], v.z, v.w);
        int d = __ldg(&dst[ebase + e]);
        atomicAdd((float4*)(agg + d * 128 + o4), v);
    }
}

// ---------------- layer 3 edge: h2 recomputed inline from agg/root2 (no combine kernel) ----
__global__ void k_l3_edge(const float* __restrict__ ea,
                          const int* __restrict__ src, const int* __restrict__ dst,
                          const float* __restrict__ w3, const float* __restrict__ b3) {
    const int lane = threadIdx.x & 31;
    const int warp = threadIdx.x >> 5;
    const int e = blockIdx.x * 8 + warp;   // 2048 blocks * 8 warps = 16384 edges
    float2 a = __ldg((const float2*)(ea + 2 * e));
    int s = __ldg(&src[e]);
    float inv_s = 1.f / fmaxf(g_cnt[s], 1.f);
    float s0 = 0.f, s1 = 0.f;
#pragma unroll
    for (int rep = 0; rep < 4; rep++) {
        int i = rep * 32 + lane;
        // h2[s][i] = relu(agg[s][i]*inv_s + root2[s][i])
        float h = fmaxf(fmaf(g_agg[s * 128 + i], inv_s, g_root2[s * 128 + i]), 0.f);
        int idx = 2 * i;
        float z0 = fmaf(a.y, __ldg(&w3[256 + idx]),     fmaf(a.x, __ldg(&w3[idx]),     __ldg(&b3[idx])));
        float z1 = fmaf(a.y, __ldg(&w3[256 + idx + 1]), fmaf(a.x, __ldg(&w3[idx + 1]), __ldg(&b3[idx + 1])));
        s0 = fmaf(h, fmaxf(z0, 0.f), s0);
        s1 = fmaf(h, fmaxf(z1, 0.f), s1);
    }
#pragma unroll
    for (int off = 16; off > 0; off >>= 1) {
        s0 += __shfl_down_sync(0xFFFFFFFFu, s0, off);
        s1 += __shfl_down_sync(0xFFFFFFFFu, s1, off);
    }
    if (lane == 0) {
        int d = __ldg(&dst[e]);
        atomicAdd(&g_agg3[2 * d + 0], s0);
        atomicAdd(&g_agg3[2 * d + 1], s1);
    }
}

// ---------------- layer 3 node: h2 inline, root3 = h2@r3; out; cleanup scratch ----------------
__global__ void k_l3_node(const float* __restrict__ r3, const float* __restrict__ c3,
                          float* __restrict__ out) {
    const int lane = threadIdx.x & 31;
    const int warp = threadIdx.x >> 5;
    const int n = blockIdx.x * 8 + warp;   // 512 blocks * 8 warps = 4096 nodes
    float inv = 1.f / fmaxf(g_cnt[n], 1.f);
    float s0 = 0.f, s1 = 0.f;
#pragma unroll
    for (int rep = 0; rep < 4; rep++) {
        int i = rep * 32 + lane;
        int idx = n * 128 + i;
        float h = fmaxf(fmaf(g_agg[idx], inv, g_root2[idx]), 0.f);
        g_agg[idx] = 0.f;   // re-zero agg for next replay
        s0 = fmaf(h, __ldg(&r3[2 * i + 0]), s0);
        s1 = fmaf(h, __ldg(&r3[2 * i + 1]), s1);
    }
#pragma unroll
    for (int off = 16; off > 0; off >>= 1) {
        s0 += __shfl_down_sync(0xFFFFFFFFu, s0, off);
        s1 += __shfl_down_sync(0xFFFFFFFFu, s1, off);
    }
    if (lane == 0) {
        out[2 * n + 0] = fmaf(g_agg3[2 * n + 0], inv, s0 + __ldg(&c3[0]));
        out[2 * n + 1] = fmaf(g_agg3[2 * n + 1], inv, s1 + __ldg(&c3[1]));
        // cleanup for next replay
        g_agg3[2 * n + 0] = 0.f;
        g_agg3[2 * n + 1] = 0.f;
        g_cnt[n] = 0.f;
    }
}

// ---------------- launch ----------------
// Side-stream resources: created once, on the FIRST (correctness) call — i.e.
// outside graph capture. The WORK issued per call is identical every time.
static cudaStream_t g_side = nullptr;
static cudaEvent_t  g_fork = nullptr;
static cudaEvent_t  g_join = nullptr;

extern "C" void kernel_launch(void* const* d_in, const int* in_sizes, int n_in,
                              void* d_out, int out_size) {
    const float* x   = (const float*)d_in[0];
    const float* ea  = (const float*)d_in[1];
    const int*   src = (const int*)d_in[2];
    const int*   dst = (const int*)d_in[3];
    const float* w1  = (const float*)d_in[4];
    const float* b1  = (const float*)d_in[5];
    const float* r1  = (const float*)d_in[6];
    const float* c1  = (const float*)d_in[7];
    const float* w2  = (const float*)d_in[8];
    const float* b2  = (const float*)d_in[9];
    const float* r2  = (const float*)d_in[10];
    const float* c2  = (const float*)d_in[11];
    const float* w3  = (const float*)d_in[12];
    const float* b3  = (const float*)d_in[13];
    const float* r3  = (const float*)d_in[14];
    const float* c3  = (const float*)d_in[15];
    float* out = (float*)d_out;

    if (g_side == nullptr) {
        cudaStreamCreateWithFlags(&g_side, cudaStreamNonBlocking);
        cudaEventCreateWithFlags(&g_fork, cudaEventDisableTiming);
        cudaEventCreateWithFlags(&g_join, cudaEventDisableTiming);
    }

    float* aggp;
    cudaGetSymbolAddress((void**)&aggp, g_agg);
    float* h1p;
    cudaGetSymbolAddress((void**)&h1p, g_h1);

    k_l1_edge<<<256, 256>>>(x, ea, src, dst, w1, b1);           // 1 (warp-batched, counts fused)
    k_l1_node<<<512, 256>>>(x, r1, c1);                         // 2 (root inline)

    // single fork: root2 (side) || l2_edge (main) — the one overlap that pays
    cudaEventRecord(g_fork, 0);
    cudaStreamWaitEvent(g_side, g_fork, 0);
    k_root2<<<512, 128, 0, g_side>>>(r2, c2);                   // 3 (side stream)
    k_l2_edge<<<1024, 256>>>(h1p, ea, src, dst, w2, b2, aggp);  // 4 (hot, profiled)
    cudaEventRecord(g_join, g_side);
    cudaStreamWaitEvent(0, g_join, 0);

    k_l3_edge<<<E_EDGES / 8, 256>>>(ea, src, dst, w3, b3);      // 5 (h2 inline)
    k_l3_node<<<N_NODES / 8, 256>>>(r3, c3, out);               // 6 (h2 inline + cleanup)
}

// round 16
// speedup vs baseline: 1.1113x; 1.0263x over previous
#include <cuda_runtime.h>

#define N_NODES 4096
#define E_EDGES 16384
#define HID 128

typedef unsigned long long ull;

// ---------------- scratch (device globals; zero-initialized at module load).
// Every replay restores zeroed state via k_fin, so results are deterministic.
__device__ __align__(16) float g_h1[N_NODES * HID];
__device__ __align__(16) float g_agg[N_NODES * HID];
__device__ __align__(16) float g_root2[N_NODES * HID];
__device__ __align__(16) float g_root3[N_NODES * 2];
__device__ __align__(16) float g_agg3[N_NODES * 2];
__device__ float g_cnt[N_NODES];

// ---------------- packed fp32x2 helpers (sm_100+) ----------------
__device__ __forceinline__ ull pk2(float lo, float hi) {
    ull r; asm("mov.b64 %0, {%1, %2};" : "=l"(r) : "f"(lo), "f"(hi)); return r;
}
__device__ __forceinline__ void upk2(ull v, float &lo, float &hi) {
    asm("mov.b64 {%0, %1}, %2;" : "=f"(lo), "=f"(hi) : "l"(v));
}
__device__ __forceinline__ ull ffma2(ull a, ull b, ull c) {
    ull r; asm("fma.rn.f32x2 %0, %1, %2, %3;" : "=l"(r) : "l"(a), "l"(b), "l"(c)); return r;
}
// relu(a0*w0 + a1*w1 + b) on a packed pair, single asm block.
__device__ __forceinline__ ull genrelu(ull a0, ull w0, ull a1, ull w1, ull b) {
    ull r;
    asm("{\n\t"
        ".reg .b64 z;\n\t"
        ".reg .f32 lo, hi;\n\t"
        "fma.rn.f32x2 z, %1, %2, %5;\n\t"
        "fma.rn.f32x2 z, %3, %4, z;\n\t"
        "mov.b64 {lo, hi}, z;\n\t"
        "max.f32 lo, lo, 0f00000000;\n\t"
        "max.f32 hi, hi, 0f00000000;\n\t"
        "mov.b64 %0, {lo, hi};\n\t"
        "}"
        : "=l"(r) : "l"(a0), "l"(w0), "l"(a1), "l"(w1), "l"(b));
    return r;
}

// ---------------- layer 1 edge: IN=4 -> 128, warp-batched (8 edges/warp) ----------------
__global__ void __launch_bounds__(256) k_l1_edge(
        const float* __restrict__ x, const float* __restrict__ ea,
        const int* __restrict__ src, const int* __restrict__ dst,
        const float* __restrict__ w1, const float* __restrict__ b1) {
    const int lane = threadIdx.x & 31;
    const int warp = threadIdx.x >> 5;
    const int ebase = (blockIdx.x * 8 + warp) * 8;   // 256 blocks * 8 warps * 8 edges
    const int o4 = lane << 2;

    float4 w0v[4], w1v[4], bv[4];
#pragma unroll
    for (int i = 0; i < 4; i++) {
        int idx = i * 128 + o4;
        w0v[i] = __ldg((const float4*)(w1 + idx));
        w1v[i] = __ldg((const float4*)(w1 + 512 + idx));
        bv[i]  = __ldg((const float4*)(b1 + idx));
    }

#pragma unroll
    for (int e = 0; e < 8; e++) {
        int ei = ebase + e;
        float2 a = __ldg((const float2*)(ea + 2 * ei));
        int s = __ldg(&src[ei]);
        int d = __ldg(&dst[ei]);
        float4 xs = __ldg((const float4*)(x + 4 * s));
        float xv[4] = {xs.x, xs.y, xs.z, xs.w};
        float4 acc = make_float4(0.f, 0.f, 0.f, 0.f);
#pragma unroll
        for (int i = 0; i < 4; i++) {
            acc.x = fmaf(xv[i], fmaxf(fmaf(a.y, w1v[i].x, fmaf(a.x, w0v[i].x, bv[i].x)), 0.f), acc.x);
            acc.y = fmaf(xv[i], fmaxf(fmaf(a.y, w1v[i].y, fmaf(a.x, w0v[i].y, bv[i].y)), 0.f), acc.y);
            acc.z = fmaf(xv[i], fmaxf(fmaf(a.y, w1v[i].z, fmaf(a.x, w0v[i].z, bv[i].z)), 0.f), acc.z);
            acc.w = fmaf(xv[i], fmaxf(fmaf(a.y, w1v[i].w, fmaf(a.x, w0v[i].w, bv[i].w)), 0.f), acc.w);
        }
        atomicAdd((float4*)(g_agg + d * 128 + o4), acc);
        if (lane == e) atomicAdd(&g_cnt[d], 1.f);   // fused in-degree count
    }
}

// ---------------- layer 1 node: h1 = relu(agg/cnt + x@r1 + c1); re-zero agg ----------------
__global__ void k_l1_node(const float* __restrict__ x, const float* __restrict__ r1,
                          const float* __restrict__ c1) {
    int t = blockIdx.x * blockDim.x + threadIdx.x;   // N*32 threads
    int n = t >> 5;
    int o4 = (t & 31) << 2;
    int base = n * 128 + o4;
    float inv = 1.f / fmaxf(g_cnt[n], 1.f);
    float4 xs = __ldg((const float4*)(x + 4 * n));
    float xv[4] = {xs.x, xs.y, xs.z, xs.w};
    float4 ag = *(const float4*)(g_agg + base);
    float4 root = __ldg((const float4*)(c1 + o4));
#pragma unroll
    for (int i = 0; i < 4; i++) {
        float4 rv = __ldg((const float4*)(r1 + i * 128 + o4));
        root.x = fmaf(xv[i], rv.x, root.x);
        root.y = fmaf(xv[i], rv.y, root.y);
        root.z = fmaf(xv[i], rv.z, root.z);
        root.w = fmaf(xv[i], rv.w, root.w);
    }
    float4 h;
    h.x = fmaxf(fmaf(ag.x, inv, root.x), 0.f);
    h.y = fmaxf(fmaf(ag.y, inv, root.y), 0.f);
    h.z = fmaxf(fmaf(ag.z, inv, root.z), 0.f);
    h.w = fmaxf(fmaf(ag.w, inv, root.w), 0.f);
    *(float4*)(g_h1 + base) = h;
    *(float4*)(g_agg + base) = make_float4(0.f, 0.f, 0.f, 0.f);   // ready for layer 2
}

// ---------------- layer 2 FUSED: blocks 0..255 = root2 GEMM; 256..1279 = edge kernel ----
// No streams/events: the CTA scheduler co-schedules both halves. root2 blocks
// come FIRST so wave 1 starts them immediately (overlap with edge blocks).
__global__ void __launch_bounds__(256, 2) k_l2f(
        const float* __restrict__ h1, const float* __restrict__ ea,
        const int* __restrict__ src, const int* __restrict__ dst,
        const float* __restrict__ w2, const float* __restrict__ b2,
        const float* __restrict__ r2, const float* __restrict__ c2,
        float* __restrict__ agg) {
    __shared__ __align__(16) float smW[3 * 32 * 128];   // 48 KB (edge blocks only)

    const int tid  = threadIdx.x;
    const int lane = tid & 31;
    const int warp = tid >> 5;

    if (blockIdx.x < 256) {
        // ---- root2: g_root2 = h1 @ r2 + c2 ; warp = 2 nodes ----
        const int nbase = (blockIdx.x * 8 + warp) * 2;   // 256 blocks * 8 warps * 2 = 4096
        const int o4 = lane << 2;
        const float* hp0 = h1 + nbase * 128;
        const float* hp1 = hp0 + 128;

        ull a00 = 0ull, a01 = 0ull, a10 = 0ull, a11 = 0ull;
        const ull* rp = (const ull*)r2 + (lane << 1);

        for (int i4 = 0; i4 < 128; i4 += 4) {
            float4 h0 = *(const float4*)(hp0 + i4);
            float4 h1v = *(const float4*)(hp1 + i4);
            float h0a[4] = {h0.x, h0.y, h0.z, h0.w};
            float h1a[4] = {h1v.x, h1v.y, h1v.z, h1v.w};
#pragma unroll
            for (int ii = 0; ii < 4; ii++) {
                ulonglong2 rv = __ldg((const ulonglong2*)(rp + (i4 + ii) * 64));
                ull hd0 = pk2(h0a[ii], h0a[ii]);
                ull hd1 = pk2(h1a[ii], h1a[ii]);
                a00 = ffma2(hd0, rv.x, a00);
                a01 = ffma2(hd0, rv.y, a01);
                a10 = ffma2(hd1, rv.x, a10);
                a11 = ffma2(hd1, rv.y, a11);
            }
        }

        float4 cv = __ldg((const float4*)(c2 + o4));
#pragma unroll
        for (int e = 0; e < 2; e++) {
            int base = (nbase + e) * 128 + o4;
            float v0, v1, v2, v3;
            upk2(e ? a10 : a00, v0, v1);
            upk2(e ? a11 : a01, v2, v3);
            float4 r;
            r.x = v0 + cv.x; r.y = v1 + cv.y; r.z = v2 + cv.z; r.w = v3 + cv.w;
            *(float4*)(g_root2 + base) = r;
        }
        return;
    }

    // ---- l2 edge (R10 form): block = 64 edges x one 32-i quarter ----
    const int bid = blockIdx.x - 256;            // 0..1023
    const int ibase = (bid & 3) << 5;            // i-quarter: {0,32,64,96}
    const int gblk  = bid >> 2;                  // edge block 0..255
    const int ebase = gblk * 64 + warp * 8;      // 8 edges per warp

    // cooperative stage: 3 x 1024 float4, 12 per thread
    {
        const float4* gW0 = (const float4*)(w2 + ibase * 128);
        const float4* gW1 = (const float4*)(w2 + 16384 + ibase * 128);
        const float4* gB  = (const float4*)(b2 + ibase * 128);
        float4* sm4 = (float4*)smW;
#pragma unroll
        for (int k = 0; k < 4; k++) {
            sm4[tid + k * 256]        = __ldg(gW0 + tid + k * 256);
            sm4[tid + k * 256 + 1024] = __ldg(gW1 + tid + k * 256);
            sm4[tid + k * 256 + 2048] = __ldg(gB  + tid + k * 256);
        }
    }

    ull ea0p[8], ea1p[8];
    const float* hp[8];
#pragma unroll
    for (int e = 0; e < 8; e++) {
        float2 a = __ldg((const float2*)(ea + 2 * (ebase + e)));
        ea0p[e] = pk2(a.x, a.x);
        ea1p[e] = pk2(a.y, a.y);
        hp[e] = h1 + __ldg(&src[ebase + e]) * 128 + ibase;
    }

    __syncthreads();

    ull acc0[8], acc1[8];
#pragma unroll
    for (int e = 0; e < 8; e++) { acc0[e] = 0ull; acc1[e] = 0ull; }

    const ull* sW0 = (const ull*)smW + (lane << 1);          // 2048 ull per slice
    const ull* sW1 = sW0 + 2048;
    const ull* sB  = sW0 + 4096;

    for (int i2 = 0; i2 < 32; i2 += 2) {
        float2 hv[8];
#pragma unroll
        for (int e = 0; e < 8; e++)
            hv[e] = __ldg((const float2*)(hp[e] + i2));
#pragma unroll
        for (int ii = 0; ii < 2; ii++) {
            const int woff = (i2 + ii) * 64;
            ulonglong2 w0 = *(const ulonglong2*)(sW0 + woff);
            ulonglong2 w1 = *(const ulonglong2*)(sW1 + woff);
            ulonglong2 bv = *(const ulonglong2*)(sB  + woff);
#pragma unroll
            for (int e = 0; e < 8; e++) {
                float h = ii ? hv[e].y : hv[e].x;
                ull hd = pk2(h, h);
                ull z0 = genrelu(ea0p[e], w0.x, ea1p[e], w1.x, bv.x);
                ull z1 = genrelu(ea0p[e], w0.y, ea1p[e], w1.y, bv.y);
                acc0[e] = ffma2(hd, z0, acc0[e]);
                acc1[e] = ffma2(hd, z1, acc1[e]);
            }
        }
    }

    const int o4 = lane << 2;
#pragma unroll
    for (int e = 0; e < 8; e++) {
        float4 v;
        upk2(acc0[e], v.x, v.y);
        upk2(acc1[e], v.z, v.w);
        int d = __ldg(&dst[ebase + e]);
        atomicAdd((float4*)(agg + d * 128 + o4), v);
    }
}

// ---------------- layer 3 FUSED: blocks 0..511 = root3 GEMM; 512..2559 = edge kernel ----
// h2 recomputed inline from agg/root2 in BOTH halves (read-only; cleanup in k_fin).
__global__ void k_l3f(const float* __restrict__ ea,
                      const int* __restrict__ src, const int* __restrict__ dst,
                      const float* __restrict__ w3, const float* __restrict__ b3,
                      const float* __restrict__ r3, const float* __restrict__ c3) {
    const int lane = threadIdx.x & 31;
    const int warp = threadIdx.x >> 5;

    if (blockIdx.x < 512) {
        // ---- root3: g_root3 = h2 @ r3 + c3 ; warp = 1 node ----
        const int n = blockIdx.x * 8 + warp;   // 4096 nodes
        float inv = 1.f / fmaxf(g_cnt[n], 1.f);
        float s0 = 0.f, s1 = 0.f;
#pragma unroll
        for (int rep = 0; rep < 4; rep++) {
            int i = rep * 32 + lane;
            int idx = n * 128 + i;
            float h = fmaxf(fmaf(g_agg[idx], inv, g_root2[idx]), 0.f);
            s0 = fmaf(h, __ldg(&r3[2 * i + 0]), s0);
            s1 = fmaf(h, __ldg(&r3[2 * i + 1]), s1);
        }
#pragma unroll
        for (int off = 16; off > 0; off >>= 1) {
            s0 += __shfl_down_sync(0xFFFFFFFFu, s0, off);
            s1 += __shfl_down_sync(0xFFFFFFFFu, s1, off);
        }
        if (lane == 0) {
            g_root3[2 * n + 0] = s0 + __ldg(&c3[0]);
            g_root3[2 * n + 1] = s1 + __ldg(&c3[1]);
        }
        return;
    }

    // ---- l3 edge: warp per edge, h2 inline ----
    const int e = (blockIdx.x - 512) * 8 + warp;   // 16384 edges
    float2 a = __ldg((const float2*)(ea + 2 * e));
    int s = __ldg(&src[e]);
    float inv_s = 1.f / fmaxf(g_cnt[s], 1.f);
    float s0 = 0.f, s1 = 0.f;
#pragma unroll
    for (int rep = 0; rep < 4; rep++) {
        int i = rep * 32 + lane;
        float h = fmaxf(fmaf(g_agg[s * 128 + i], inv_s, g_root2[s * 128 + i]), 0.f);
        int idx = 2 * i;
        float z0 = fmaf(a.y, __ldg(&w3[256 + idx]),     fmaf(a.x, __ldg(&w3[idx]),     __ldg(&b3[idx])));
        float z1 = fmaf(a.y, __ldg(&w3[256 + idx + 1]), fmaf(a.x, __ldg(&w3[idx + 1]), __ldg(&b3[idx + 1])));
        s0 = fmaf(h, fmaxf(z0, 0.f), s0);
        s1 = fmaf(h, fmaxf(z1, 0.f), s1);
    }
#pragma unroll
    for (int off = 16; off > 0; off >>= 1) {
        s0 += __shfl_down_sync(0xFFFFFFFFu, s0, off);
        s1 += __shfl_down_sync(0xFFFFFFFFu, s1, off);
    }
    if (lane == 0) {
        int d = __ldg(&dst[e]);
        atomicAdd(&g_agg3[2 * d + 0], s0);
        atomicAdd(&g_agg3[2 * d + 1], s1);
    }
}

// ---------------- final: out = agg3/cnt + root3; re-zero ALL scratch ----------------
__global__ void k_fin(float* __restrict__ out) {
    int t = blockIdx.x * blockDim.x + threadIdx.x;   // N*32 threads
    int n = t >> 5;
    int o4 = (t & 31) << 2;
    *(float4*)(g_agg + n * 128 + o4) = make_float4(0.f, 0.f, 0.f, 0.f);
    if ((t & 31) == 0) {
        float inv = 1.f / fmaxf(g_cnt[n], 1.f);
        out[2 * n + 0] = fmaf(g_agg3[2 * n + 0], inv, g_root3[2 * n + 0]);
        out[2 * n + 1] = fmaf(g_agg3[2 * n + 1], inv, g_root3[2 * n + 1]);
        g_agg3[2 * n + 0] = 0.f;
        g_agg3[2 * n + 1] = 0.f;
        g_cnt[n] = 0.f;
    }
}

// ---------------- launch: 5 kernels, one stream, zero events ----------------
extern "C" void kernel_launch(void* const* d_in, const int* in_sizes, int n_in,
                              void* d_out, int out_size) {
    const float* x   = (const float*)d_in[0];
    const float* ea  = (const float*)d_in[1];
    const int*   src = (const int*)d_in[2];
    const int*   dst = (const int*)d_in[3];
    const float* w1  = (const float*)d_in[4];
    const float* b1  = (const float*)d_in[5];
    const float* r1  = (const float*)d_in[6];
    const float* c1  = (const float*)d_in[7];
    const float* w2  = (const float*)d_in[8];
    const float* b2  = (const float*)d_in[9];
    const float* r2  = (const float*)d_in[10];
    const float* c2  = (const float*)d_in[11];
    const float* w3  = (const float*)d_in[12];
    const float* b3  = (const float*)d_in[13];
    const float* r3  = (const float*)d_in[14];
    const float* c3  = (const float*)d_in[15];
    float* out = (float*)d_out;

    float* aggp;
    cudaGetSymbolAddress((void**)&aggp, g_agg);
    float* h1p;
    cudaGetSymbolAddress((void**)&h1p, g_h1);

    k_l1_edge<<<256, 256>>>(x, ea, src, dst, w1, b1);                       // 1
    k_l1_node<<<512, 256>>>(x, r1, c1);                                     // 2
    k_l2f<<<1280, 256>>>(h1p, ea, src, dst, w2, b2, r2, c2, aggp);          // 3 (root2 + edge)
    k_l3f<<<2560, 256>>>(ea, src, dst, w3, b3, r3, c3);                     // 4 (root3 + edge)
    k_fin<<<512, 256>>>(out);                                               // 5
}

// round 17
// speedup vs baseline: 1.1143x; 1.0027x over previous
#include <cuda_runtime.h>

#define N_NODES 4096
#define E_EDGES 16384
#define HID 128

typedef unsigned long long ull;

// ---------------- scratch (device globals; zero-initialized at module load).
// Every replay restores zeroed state via k_fin, so results are deterministic.
__device__ __align__(16) float g_h1[N_NODES * HID];
__device__ __align__(16) float g_agg[N_NODES * HID];
__device__ __align__(16) float g_root2[N_NODES * HID];
__device__ __align__(16) float g_root3[N_NODES * 2];
__device__ __align__(16) float g_agg3[N_NODES * 2];
__device__ float g_cnt[N_NODES];

// ---------------- packed fp32x2 helpers (sm_100+) ----------------
__device__ __forceinline__ ull pk2(float lo, float hi) {
    ull r; asm("mov.b64 %0, {%1, %2};" : "=l"(r) : "f"(lo), "f"(hi)); return r;
}
__device__ __forceinline__ void upk2(ull v, float &lo, float &hi) {
    asm("mov.b64 {%0, %1}, %2;" : "=f"(lo), "=f"(hi) : "l"(v));
}
__device__ __forceinline__ ull ffma2(ull a, ull b, ull c) {
    ull r; asm("fma.rn.f32x2 %0, %1, %2, %3;" : "=l"(r) : "l"(a), "l"(b), "l"(c)); return r;
}
// relu(a0*w0 + a1*w1 + b) on a packed pair, single asm block.
__device__ __forceinline__ ull genrelu(ull a0, ull w0, ull a1, ull w1, ull b) {
    ull r;
    asm("{\n\t"
        ".reg .b64 z;\n\t"
        ".reg .f32 lo, hi;\n\t"
        "fma.rn.f32x2 z, %1, %2, %5;\n\t"
        "fma.rn.f32x2 z, %3, %4, z;\n\t"
        "mov.b64 {lo, hi}, z;\n\t"
        "max.f32 lo, lo, 0f00000000;\n\t"
        "max.f32 hi, hi, 0f00000000;\n\t"
        "mov.b64 %0, {lo, hi};\n\t"
        "}"
        : "=l"(r) : "l"(a0), "l"(w0), "l"(a1), "l"(w1), "l"(b));
    return r;
}

// ---------------- layer 1 edge: IN=4 -> 128, warp-batched (8 edges/warp) ----------------
__global__ void __launch_bounds__(256) k_l1_edge(
        const float* __restrict__ x, const float* __restrict__ ea,
        const int* __restrict__ src, const int* __restrict__ dst,
        const float* __restrict__ w1, const float* __restrict__ b1) {
    const int lane = threadIdx.x & 31;
    const int warp = threadIdx.x >> 5;
    const int ebase = (blockIdx.x * 8 + warp) * 8;   // 256 blocks * 8 warps * 8 edges
    const int o4 = lane << 2;

    float4 w0v[4], w1v[4], bv[4];
#pragma unroll
    for (int i = 0; i < 4; i++) {
        int idx = i * 128 + o4;
        w0v[i] = __ldg((const float4*)(w1 + idx));
        w1v[i] = __ldg((const float4*)(w1 + 512 + idx));
        bv[i]  = __ldg((const float4*)(b1 + idx));
    }

#pragma unroll
    for (int e = 0; e < 8; e++) {
        int ei = ebase + e;
        float2 a = __ldg((const float2*)(ea + 2 * ei));
        int s = __ldg(&src[ei]);
        int d = __ldg(&dst[ei]);
        float4 xs = __ldg((const float4*)(x + 4 * s));
        float xv[4] = {xs.x, xs.y, xs.z, xs.w};
        float4 acc = make_float4(0.f, 0.f, 0.f, 0.f);
#pragma unroll
        for (int i = 0; i < 4; i++) {
            acc.x = fmaf(xv[i], fmaxf(fmaf(a.y, w1v[i].x, fmaf(a.x, w0v[i].x, bv[i].x)), 0.f), acc.x);
            acc.y = fmaf(xv[i], fmaxf(fmaf(a.y, w1v[i].y, fmaf(a.x, w0v[i].y, bv[i].y)), 0.f), acc.y);
            acc.z = fmaf(xv[i], fmaxf(fmaf(a.y, w1v[i].z, fmaf(a.x, w0v[i].z, bv[i].z)), 0.f), acc.z);
            acc.w = fmaf(xv[i], fmaxf(fmaf(a.y, w1v[i].w, fmaf(a.x, w0v[i].w, bv[i].w)), 0.f), acc.w);
        }
        atomicAdd((float4*)(g_agg + d * 128 + o4), acc);
        if (lane == e) atomicAdd(&g_cnt[d], 1.f);   // fused in-degree count
    }
}

// ---------------- layer 1 node: h1 = relu(agg/cnt + x@r1 + c1); re-zero agg ----------------
__global__ void k_l1_node(const float* __restrict__ x, const float* __restrict__ r1,
                          const float* __restrict__ c1) {
    int t = blockIdx.x * blockDim.x + threadIdx.x;   // N*32 threads
    int n = t >> 5;
    int o4 = (t & 31) << 2;
    int base = n * 128 + o4;
    float inv = 1.f / fmaxf(g_cnt[n], 1.f);
    float4 xs = __ldg((const float4*)(x + 4 * n));
    float xv[4] = {xs.x, xs.y, xs.z, xs.w};
    float4 ag = *(const float4*)(g_agg + base);
    float4 root = __ldg((const float4*)(c1 + o4));
#pragma unroll
    for (int i = 0; i < 4; i++) {
        float4 rv = __ldg((const float4*)(r1 + i * 128 + o4));
        root.x = fmaf(xv[i], rv.x, root.x);
        root.y = fmaf(xv[i], rv.y, root.y);
        root.z = fmaf(xv[i], rv.z, root.z);
        root.w = fmaf(xv[i], rv.w, root.w);
    }
    float4 h;
    h.x = fmaxf(fmaf(ag.x, inv, root.x), 0.f);
    h.y = fmaxf(fmaf(ag.y, inv, root.y), 0.f);
    h.z = fmaxf(fmaf(ag.z, inv, root.z), 0.f);
    h.w = fmaxf(fmaf(ag.w, inv, root.w), 0.f);
    *(float4*)(g_h1 + base) = h;
    *(float4*)(g_agg + base) = make_float4(0.f, 0.f, 0.f, 0.f);   // ready for layer 2
}

// ---------------- layer 2 FUSED: blocks 0..255 = root2 GEMM; 256..1279 = edge kernel ----
__global__ void __launch_bounds__(256, 2) k_l2f(
        const float* __restrict__ h1, const float* __restrict__ ea,
        const int* __restrict__ src, const int* __restrict__ dst,
        const float* __restrict__ w2, const float* __restrict__ b2,
        const float* __restrict__ r2, const float* __restrict__ c2,
        float* __restrict__ agg) {
    __shared__ __align__(16) float smW[3 * 32 * 128];   // 48 KB (edge blocks only)

    const int tid  = threadIdx.x;
    const int lane = tid & 31;
    const int warp = tid >> 5;

    if (blockIdx.x < 256) {
        // ---- root2: g_root2 = h1 @ r2 + c2 ; warp = 2 nodes ----
        const int nbase = (blockIdx.x * 8 + warp) * 2;   // 256 blocks * 8 warps * 2 = 4096
        const int o4 = lane << 2;
        const float* hp0 = h1 + nbase * 128;
        const float* hp1 = hp0 + 128;

        ull a00 = 0ull, a01 = 0ull, a10 = 0ull, a11 = 0ull;
        const ull* rp = (const ull*)r2 + (lane << 1);

        for (int i4 = 0; i4 < 128; i4 += 4) {
            float4 h0 = *(const float4*)(hp0 + i4);
            float4 h1v = *(const float4*)(hp1 + i4);
            float h0a[4] = {h0.x, h0.y, h0.z, h0.w};
            float h1a[4] = {h1v.x, h1v.y, h1v.z, h1v.w};
#pragma unroll
            for (int ii = 0; ii < 4; ii++) {
                ulonglong2 rv = __ldg((const ulonglong2*)(rp + (i4 + ii) * 64));
                ull hd0 = pk2(h0a[ii], h0a[ii]);
                ull hd1 = pk2(h1a[ii], h1a[ii]);
                a00 = ffma2(hd0, rv.x, a00);
                a01 = ffma2(hd0, rv.y, a01);
                a10 = ffma2(hd1, rv.x, a10);
                a11 = ffma2(hd1, rv.y, a11);
            }
        }

        float4 cv = __ldg((const float4*)(c2 + o4));
#pragma unroll
        for (int e = 0; e < 2; e++) {
            int base = (nbase + e) * 128 + o4;
            float v0, v1, v2, v3;
            upk2(e ? a10 : a00, v0, v1);
            upk2(e ? a11 : a01, v2, v3);
            float4 r;
            r.x = v0 + cv.x; r.y = v1 + cv.y; r.z = v2 + cv.z; r.w = v3 + cv.w;
            *(float4*)(g_root2 + base) = r;
        }
        return;
    }

    // ---- l2 edge (R10 form): block = 64 edges x one 32-i quarter ----
    const int bid = blockIdx.x - 256;            // 0..1023
    const int ibase = (bid & 3) << 5;            // i-quarter: {0,32,64,96}
    const int gblk  = bid >> 2;                  // edge block 0..255
    const int ebase = gblk * 64 + warp * 8;      // 8 edges per warp

    // cooperative stage: 3 x 1024 float4, 12 per thread
    {
        const float4* gW0 = (const float4*)(w2 + ibase * 128);
        const float4* gW1 = (const float4*)(w2 + 16384 + ibase * 128);
        const float4* gB  = (const float4*)(b2 + ibase * 128);
        float4* sm4 = (float4*)smW;
#pragma unroll
        for (int k = 0; k < 4; k++) {
            sm4[tid + k * 256]        = __ldg(gW0 + tid + k * 256);
            sm4[tid + k * 256 + 1024] = __ldg(gW1 + tid + k * 256);
            sm4[tid + k * 256 + 2048] = __ldg(gB  + tid + k * 256);
        }
    }

    ull ea0p[8], ea1p[8];
    const float* hp[8];
#pragma unroll
    for (int e = 0; e < 8; e++) {
        float2 a = __ldg((const float2*)(ea + 2 * (ebase + e)));
        ea0p[e] = pk2(a.x, a.x);
        ea1p[e] = pk2(a.y, a.y);
        hp[e] = h1 + __ldg(&src[ebase + e]) * 128 + ibase;
    }

    __syncthreads();

    ull acc0[8], acc1[8];
#pragma unroll
    for (int e = 0; e < 8; e++) { acc0[e] = 0ull; acc1[e] = 0ull; }

    const ull* sW0 = (const ull*)smW + (lane << 1);          // 2048 ull per slice
    const ull* sW1 = sW0 + 2048;
    const ull* sB  = sW0 + 4096;

    for (int i2 = 0; i2 < 32; i2 += 2) {
        float2 hv[8];
#pragma unroll
        for (int e = 0; e < 8; e++)
            hv[e] = __ldg((const float2*)(hp[e] + i2));
#pragma unroll
        for (int ii = 0; ii < 2; ii++) {
            const int woff = (i2 + ii) * 64;
            ulonglong2 w0 = *(const ulonglong2*)(sW0 + woff);
            ulonglong2 w1 = *(const ulonglong2*)(sW1 + woff);
            ulonglong2 bv = *(const ulonglong2*)(sB  + woff);
#pragma unroll
            for (int e = 0; e < 8; e++) {
                float h = ii ? hv[e].y : hv[e].x;
                ull hd = pk2(h, h);
                ull z0 = genrelu(ea0p[e], w0.x, ea1p[e], w1.x, bv.x);
                ull z1 = genrelu(ea0p[e], w0.y, ea1p[e], w1.y, bv.y);
                acc0[e] = ffma2(hd, z0, acc0[e]);
                acc1[e] = ffma2(hd, z1, acc1[e]);
            }
        }
    }

    const int o4 = lane << 2;
#pragma unroll
    for (int e = 0; e < 8; e++) {
        float4 v;
        upk2(acc0[e], v.x, v.y);
        upk2(acc1[e], v.z, v.w);
        int d = __ldg(&dst[ebase + e]);
        atomicAdd((float4*)(agg + d * 128 + o4), v);
    }
}

// ---------------- layer 3 FUSED: blocks 0..511 = root3 GEMM; 512..1023 = edge (4 edges/warp) ----
// h2 recomputed inline from agg/root2 in BOTH halves (read-only; cleanup in k_fin).
// Edge half preloads its w3/b3 slice ONCE per warp (12 LDG) and reuses it for
// 4 edges — cuts per-warp LDG from 128 to ~56 (LSU-floor relief).
__global__ void __launch_bounds__(256) k_l3f(
        const float* __restrict__ ea,
        const int* __restrict__ src, const int* __restrict__ dst,
        const float* __restrict__ w3, const float* __restrict__ b3,
        const float* __restrict__ r3, const float* __restrict__ c3) {
    const int lane = threadIdx.x & 31;
    const int warp = threadIdx.x >> 5;

    if (blockIdx.x < 512) {
        // ---- root3: g_root3 = h2 @ r3 + c3 ; warp = 1 node ----
        const int n = blockIdx.x * 8 + warp;   // 4096 nodes
        float inv = 1.f / fmaxf(g_cnt[n], 1.f);
        float s0 = 0.f, s1 = 0.f;
#pragma unroll
        for (int rep = 0; rep < 4; rep++) {
            int i = rep * 32 + lane;
            int idx = n * 128 + i;
            float h = fmaxf(fmaf(g_agg[idx], inv, g_root2[idx]), 0.f);
            s0 = fmaf(h, __ldg(&r3[2 * i + 0]), s0);
            s1 = fmaf(h, __ldg(&r3[2 * i + 1]), s1);
        }
#pragma unroll
        for (int off = 16; off > 0; off >>= 1) {
            s0 += __shfl_down_sync(0xFFFFFFFFu, s0, off);
            s1 += __shfl_down_sync(0xFFFFFFFFu, s1, off);
        }
        if (lane == 0) {
            g_root3[2 * n + 0] = s0 + __ldg(&c3[0]);
            g_root3[2 * n + 1] = s1 + __ldg(&c3[1]);
        }
        return;
    }

    // ---- l3 edge: warp = 4 edges, w3/b3 preloaded once ----
    const int ebase = ((blockIdx.x - 512) * 8 + warp) * 4;   // 512 blocks * 8 warps * 4 = 16384

    float2 wl[4], wh[4], bb[4];
#pragma unroll
    for (int rep = 0; rep < 4; rep++) {
        int idx = 2 * (rep * 32 + lane);
        wl[rep] = __ldg((const float2*)(w3 + idx));
        wh[rep] = __ldg((const float2*)(w3 + 256 + idx));
        bb[rep] = __ldg((const float2*)(b3 + idx));
    }

    float2 av[4];
    int sv[4];
    float invv[4];
#pragma unroll
    for (int e = 0; e < 4; e++) {
        av[e] = __ldg((const float2*)(ea + 2 * (ebase + e)));
        sv[e] = __ldg(&src[ebase + e]) * 128;
        invv[e] = 1.f / fmaxf(g_cnt[sv[e] >> 7], 1.f);
    }

    float s0[4] = {0.f, 0.f, 0.f, 0.f};
    float s1[4] = {0.f, 0.f, 0.f, 0.f};
#pragma unroll
    for (int rep = 0; rep < 4; rep++) {
        int i = rep * 32 + lane;
        // z values per edge from the shared preloaded w slice
#pragma unroll
        for (int e = 0; e < 4; e++) {
            float h = fmaxf(fmaf(g_agg[sv[e] + i], invv[e], g_root2[sv[e] + i]), 0.f);
            float z0 = fmaxf(fmaf(av[e].y, wh[rep].x, fmaf(av[e].x, wl[rep].x, bb[rep].x)), 0.f);
            float z1 = fmaxf(fmaf(av[e].y, wh[rep].y, fmaf(av[e].x, wl[rep].y, bb[rep].y)), 0.f);
            s0[e] = fmaf(h, z0, s0[e]);
            s1[e] = fmaf(h, z1, s1[e]);
        }
    }

#pragma unroll
    for (int off = 16; off > 0; off >>= 1) {
#pragma unroll
        for (int e = 0; e < 4; e++) {
            s0[e] += __shfl_down_sync(0xFFFFFFFFu, s0[e], off);
            s1[e] += __shfl_down_sync(0xFFFFFFFFu, s1[e], off);
        }
    }
    if (lane == 0) {
#pragma unroll
        for (int e = 0; e < 4; e++) {
            int d = __ldg(&dst[ebase + e]);
            atomicAdd(&g_agg3[2 * d + 0], s0[e]);
            atomicAdd(&g_agg3[2 * d + 1], s1[e]);
        }
    }
}

// ---------------- final: out = agg3/cnt + root3; re-zero ALL scratch ----------------
__global__ void k_fin(float* __restrict__ out) {
    int t = blockIdx.x * blockDim.x + threadIdx.x;   // N*32 threads
    int n = t >> 5;
    int o4 = (t & 31) << 2;
    *(float4*)(g_agg + n * 128 + o4) = make_float4(0.f, 0.f, 0.f, 0.f);
    if ((t & 31) == 0) {
        float inv = 1.f / fmaxf(g_cnt[n], 1.f);
        out[2 * n + 0] = fmaf(g_agg3[2 * n + 0], inv, g_root3[2 * n + 0]);
        out[2 * n + 1] = fmaf(g_agg3[2 * n + 1], inv, g_root3[2 * n + 1]);
        g_agg3[2 * n + 0] = 0.f;
        g_agg3[2 * n + 1] = 0.f;
        g_cnt[n] = 0.f;
    }
}

// ---------------- launch: 5 kernels, one stream, zero events ----------------
extern "C" void kernel_launch(void* const* d_in, const int* in_sizes, int n_in,
                              void* d_out, int out_size) {
    const float* x   = (const float*)d_in[0];
    const float* ea  = (const float*)d_in[1];
    const int*   src = (const int*)d_in[2];
    const int*   dst = (const int*)d_in[3];
    const float* w1  = (const float*)d_in[4];
    const float* b1  = (const float*)d_in[5];
    const float* r1  = (const float*)d_in[6];
    const float* c1  = (const float*)d_in[7];
    const float* w2  = (const float*)d_in[8];
    const float* b2  = (const float*)d_in[9];
    const float* r2  = (const float*)d_in[10];
    const float* c2  = (const float*)d_in[11];
    const float* w3  = (const float*)d_in[12];
    const float* b3  = (const float*)d_in[13];
    const float* r3  = (const float*)d_in[14];
    const float* c3  = (const float*)d_in[15];
    float* out = (float*)d_out;

    float* aggp;
    cudaGetSymbolAddress((void**)&aggp, g_agg);
    float* h1p;
    cudaGetSymbolAddress((void**)&h1p, g_h1);

    k_l1_edge<<<256, 256>>>(x, ea, src, dst, w1, b1);                       // 1
    k_l1_node<<<512, 256>>>(x, r1, c1);                                     // 2
    k_l2f<<<1280, 256>>>(h1p, ea, src, dst, w2, b2, r2, c2, aggp);          // 3 (root2 + edge)
    k_l3f<<<1024, 256>>>(ea, src, dst, w3, b3, r3, c3);                     // 4 (root3 + edge, 4e/warp)
    k_fin<<<512, 256>>>(out);                                               // 5
}